// round 3
// baseline (speedup 1.0000x reference)
#include <cuda_runtime.h>
#include <cstdint>

// ---------------- problem constants ----------------
#define NNZ      220939
#define CIN      32
#define COUT     64
#define KVOL     27
#define OUT_X    11
#define OUT_Y    400
#define OUT_Z    352

// ---------------- device scratch (static, allocation-free) ----------------
__device__ int2 g_rules[(size_t)KVOL * NNZ];          // 47.7 MB rulebook
__device__ int  g_cnt[KVOL * 128];                    // counters, 512B apart

// ---------------- f32x2 helpers ----------------
#define FFMA2(d, a, b, c) \
    asm("fma.rn.f32x2 %0, %1, %2, %3;" : "=l"(d) : "l"(a), "l"(b), "l"(c))

// ---------------- kernel 1: zero output + counters (fused) ------------------
__global__ void zero_all(float4* __restrict__ out4, long long n4) {
    if (blockIdx.x == 0 && threadIdx.x < KVOL)
        g_cnt[threadIdx.x * 128] = 0;
    long long i = (long long)blockIdx.x * blockDim.x + threadIdx.x;
    long long step = (long long)gridDim.x * blockDim.x;
    float4 z = make_float4(0.f, 0.f, 0.f, 0.f);
    for (; i < n4; i += step) out4[i] = z;
}

// ---------------- kernel 2: build rulebook (warp-aggregated atomics) --------
__global__ void build_rules(const int* __restrict__ coords, int n) {
    int i    = blockIdx.x * blockDim.x + threadIdx.x;
    int lane = threadIdx.x & 31;
    bool active = (i < n);

    int cx = 0, cy = 0, cz = 0;
    if (active) {
        cx = coords[i * 3 + 0];
        cy = coords[i * 3 + 1];
        cz = coords[i * 3 + 2];
    }

    bool vX[3], vY[3], vZ[3];
    int  qX[3], qY[3], qZ[3];
#pragma unroll
    for (int o = 0; o < 3; o++) {
        int ox = cx + 1 - o; vX[o] = (ox >= 0) && !(ox & 1) && ((ox >> 1) < OUT_X); qX[o] = ox >> 1;
        int oy = cy + 1 - o; vY[o] = (oy >= 0) && !(oy & 1) && ((oy >> 1) < OUT_Y); qY[o] = oy >> 1;
        int oz = cz + 1 - o; vZ[o] = (oz >= 0) && !(oz & 1) && ((oz >> 1) < OUT_Z); qZ[o] = oz >> 1;
    }

#pragma unroll
    for (int kx = 0; kx < 3; kx++) {
#pragma unroll
        for (int ky = 0; ky < 3; ky++) {
#pragma unroll
            for (int kz = 0; kz < 3; kz++) {
                int k = (kx * 3 + ky) * 3 + kz;
                bool valid = active && vX[kx] && vY[ky] && vZ[kz];
                int flat = 0;
                if (valid) flat = (qX[kx] * OUT_Y + qY[ky]) * OUT_Z + qZ[kz];

                unsigned mask = __ballot_sync(0xffffffffu, valid);
                if (mask) {
                    int leader = __ffs(mask) - 1;
                    int base = 0;
                    if (lane == leader)
                        base = atomicAdd(&g_cnt[k * 128], __popc(mask));
                    base = __shfl_sync(0xffffffffu, base, leader);
                    if (valid) {
                        int pos = base + __popc(mask & ((1u << lane) - 1u));
                        g_rules[(size_t)k * NNZ + pos] = make_int2(i, flat);
                    }
                }
            }
        }
    }
}

// ---------------- kernel 3: gather-GEMM-scatter per offset -------------------
// block 256 = 8 concurrent points x 32 cout-pairs. Each thread owns 2 adjacent
// output channels; its 2 weight columns live as 32 packed f32x2 registers
// (W rows are contiguous pairs). Features are staged PRE-SPLATTED in shared
// ((f,f) u64 per cin), read as broadcast LDS.128 (2 cin per load). Inner loop:
// 16 LDS.128 + 32 FFMA2 per point, two independent acc chains.
// Scatter: one red.global.add.v2.f32 per thread -> contiguous 256B per warp.
#define TILE_P  128
#define GROUP_P 16

__global__ __launch_bounds__(256, 2)
void gather_gemm_scatter(const float* __restrict__ features,
                         const float* __restrict__ weight,
                         float* __restrict__ out) {
    const int k   = blockIdx.y;
    const int cnt = g_cnt[k * 128];
    if ((int)blockIdx.x * TILE_P >= cnt) return;

    const int tid   = threadIdx.x;
    const int cp    = tid & 31;             // cout pair index (cout = 2*cp)
    const int pbase = tid >> 5;             // 0..7

    // Pack weight columns W[k][c][2cp..2cp+1] for c=0..31 into 32 f32x2 regs.
    unsigned long long w2[CIN];
    {
        const float2* wk = (const float2*)(weight + (size_t)k * (CIN * COUT)) + cp;
#pragma unroll
        for (int c = 0; c < CIN; c++) {
            float2 w = wk[c * (COUT / 2)];
            asm("mov.b64 %0, {%1, %2};" : "=l"(w2[c]) : "f"(w.x), "f"(w.y));
        }
    }

    __shared__ __align__(16) unsigned long long sf2[GROUP_P][CIN]; // splatted feats
    __shared__ int sflat[GROUP_P];

    const int2* rules_k = g_rules + (size_t)k * NNZ;

    for (int tile = blockIdx.x; tile * TILE_P < cnt; tile += gridDim.x) {
        const int base = tile * TILE_P;
        for (int g0 = 0; g0 < TILE_P; g0 += GROUP_P) {
            __syncthreads();
            // stage GROUP_P points: 512 splatted values, 2 per thread
#pragma unroll
            for (int e = tid; e < GROUP_P * CIN; e += 256) {
                int p = e >> 5;
                int c = e & 31;
                int j = base + g0 + p;
                if (j < cnt) {
                    int2 r = rules_k[j];
                    float f = features[(size_t)r.x * CIN + c];
                    unsigned long long s;
                    asm("mov.b64 %0, {%1, %1};" : "=l"(s) : "f"(f));
                    sf2[p][c] = s;
                    if (c == 0) sflat[p] = r.y;
                }
            }
            __syncthreads();

#pragma unroll
            for (int pp = 0; pp < GROUP_P; pp += 8) {
                int p = pbase + pp;
                int j = base + g0 + p;
                if (j < cnt) {
                    unsigned long long acc0 = 0ull, acc1 = 0ull;
                    const ulonglong2* f2 = (const ulonglong2*)sf2[p];
#pragma unroll
                    for (int q = 0; q < CIN / 2; q++) {
                        ulonglong2 u = f2[q];
                        FFMA2(acc0, u.x, w2[2 * q + 0], acc0);
                        FFMA2(acc1, u.y, w2[2 * q + 1], acc1);
                    }
                    unsigned long long accs;
                    asm("add.rn.f32x2 %0, %1, %2;" : "=l"(accs) : "l"(acc0), "l"(acc1));
                    float r0, r1;
                    asm("mov.b64 {%0, %1}, %2;" : "=f"(r0), "=f"(r1) : "l"(accs));
                    const float* dst = out + (size_t)sflat[p] * COUT + 2 * cp;
                    asm volatile(
                        "{ .reg .u64 pg; cvta.to.global.u64 pg, %0;\n\t"
                        "  red.global.add.v2.f32 [pg], {%1, %2}; }"
                        :: "l"(dst), "f"(r0), "f"(r1) : "memory");
                }
            }
        }
    }
}

// ---------------- launch ----------------
extern "C" void kernel_launch(void* const* d_in, const int* in_sizes, int n_in,
                              void* d_out, int out_size) {
    const float* features = (const float*)d_in[0];
    const int*   coords   = (const int*)d_in[1];
    const float* weight   = (const float*)d_in[2];
    float*       out      = (float*)d_out;

    // 1) zero output (poisoned) + counters in one kernel
    long long n4 = (long long)out_size / 4;
    zero_all<<<4096, 256>>>((float4*)out, n4);

    // 2) rulebook
    build_rules<<<(NNZ + 255) / 256, 256>>>(coords, NNZ);

    // 3) gather-GEMM-scatter, one kernel offset per blockIdx.y
    int tiles = (NNZ + TILE_P - 1) / TILE_P;
    dim3 grid(tiles < 256 ? tiles : 256, KVOL);
    gather_gemm_scatter<<<grid, 256>>>(features, weight, out);
}

// round 4
// speedup vs baseline: 1.1980x; 1.1980x over previous
#include <cuda_runtime.h>
#include <cstdint>

// ---------------- problem constants ----------------
#define NNZ      220939
#define CIN      32
#define COUT     64
#define KVOL     27
#define OUT_X    11
#define OUT_Y    400
#define OUT_Z    352

// ---------------- device scratch (static, allocation-free) ----------------
__device__ int2 g_rules[(size_t)KVOL * NNZ];          // 47.7 MB rulebook
__device__ int  g_cnt[KVOL * 128];                    // counters, 512B apart
__device__ int  g_done;                               // gemm block-completion ctr

// ---------------- f32x2 helpers ----------------
#define FFMA2(d, a, b, c) \
    asm("fma.rn.f32x2 %0, %1, %2, %3;" : "=l"(d) : "l"(a), "l"(b), "l"(c))

// ---------------- kernel A: fused zero-output + build-rulebook ---------------
// First BUILD_BLOCKS blocks build the rulebook (counters are zero on entry:
// static-init on first call, reset by the gemm epilogue on every call).
// Remaining blocks stream-zero the 396 MB output; the ~15us build hides
// under the ~55us DRAM fill.
#define BUILD_BLOCKS 864   // ceil(NNZ/256)
#define ZERO_BLOCKS  4096

__global__ void zero_and_build(float4* __restrict__ out4, long long n4,
                               const int* __restrict__ coords) {
    if (blockIdx.x >= BUILD_BLOCKS) {
        long long i = (long long)(blockIdx.x - BUILD_BLOCKS) * blockDim.x + threadIdx.x;
        long long step = (long long)ZERO_BLOCKS * blockDim.x;
        float4 z = make_float4(0.f, 0.f, 0.f, 0.f);
        for (; i < n4; i += step) out4[i] = z;
        return;
    }

    int i    = blockIdx.x * blockDim.x + threadIdx.x;
    int lane = threadIdx.x & 31;
    bool active = (i < NNZ);

    int cx = 0, cy = 0, cz = 0;
    if (active) {
        cx = coords[i * 3 + 0];
        cy = coords[i * 3 + 1];
        cz = coords[i * 3 + 2];
    }

    bool vX[3], vY[3], vZ[3];
    int  qX[3], qY[3], qZ[3];
#pragma unroll
    for (int o = 0; o < 3; o++) {
        int ox = cx + 1 - o; vX[o] = (ox >= 0) && !(ox & 1) && ((ox >> 1) < OUT_X); qX[o] = ox >> 1;
        int oy = cy + 1 - o; vY[o] = (oy >= 0) && !(oy & 1) && ((oy >> 1) < OUT_Y); qY[o] = oy >> 1;
        int oz = cz + 1 - o; vZ[o] = (oz >= 0) && !(oz & 1) && ((oz >> 1) < OUT_Z); qZ[o] = oz >> 1;
    }

#pragma unroll
    for (int kx = 0; kx < 3; kx++) {
#pragma unroll
        for (int ky = 0; ky < 3; ky++) {
#pragma unroll
            for (int kz = 0; kz < 3; kz++) {
                int k = (kx * 3 + ky) * 3 + kz;
                bool valid = active && vX[kx] && vY[ky] && vZ[kz];
                int flat = 0;
                if (valid) flat = (qX[kx] * OUT_Y + qY[ky]) * OUT_Z + qZ[kz];

                unsigned mask = __ballot_sync(0xffffffffu, valid);
                if (mask) {
                    int leader = __ffs(mask) - 1;
                    int base = 0;
                    if (lane == leader)
                        base = atomicAdd(&g_cnt[k * 128], __popc(mask));
                    base = __shfl_sync(0xffffffffu, base, leader);
                    if (valid) {
                        int pos = base + __popc(mask & ((1u << lane) - 1u));
                        g_rules[(size_t)k * NNZ + pos] = make_int2(i, flat);
                    }
                }
            }
        }
    }
}

// ---------------- kernel B: gather-GEMM-scatter per offset -------------------
// R1 layout (proven): block 256 = 4 point-slots x 64 couts; each thread owns
// ONE cout with its 32-long weight column in 16 f32x2 registers; features
// staged in shared, read as broadcast LDS.128. New: shuffle-collect groups of
// 4 adjacent couts -> one red.global.add.v4.f32 per 4 channels (atomic
// lane-ops cut 4x). Epilogue: last finished block resets counters for the
// next graph replay.
#define TILE_P  128
#define GROUP_P 16
#define GEMM_GX 256

__global__ __launch_bounds__(256, 6)
void gather_gemm_scatter(const float* __restrict__ features,
                         const float* __restrict__ weight,
                         float* __restrict__ out) {
    const int k   = blockIdx.y;
    const int cnt = g_cnt[k * 128];

    const int tid   = threadIdx.x;
    const int cout  = tid & 63;
    const int pbase = tid >> 6;             // 0..3

    if ((int)blockIdx.x * TILE_P < cnt) {
        // Pack this thread's weight column W[k][:, cout] into 16 f32x2 regs.
        unsigned long long w2[16];
        {
            const float* wk = weight + (size_t)k * (CIN * COUT) + cout;
#pragma unroll
            for (int q = 0; q < 16; q++) {
                float w0 = wk[(2 * q + 0) * COUT];
                float w1 = wk[(2 * q + 1) * COUT];
                asm("mov.b64 %0, {%1, %2};" : "=l"(w2[q]) : "f"(w0), "f"(w1));
            }
        }

        __shared__ __align__(16) float sf[GROUP_P][CIN];
        __shared__ int sflat[GROUP_P];

        const int2* rules_k = g_rules + (size_t)k * NNZ;

        for (int tile = blockIdx.x; tile * TILE_P < cnt; tile += GEMM_GX) {
            const int base = tile * TILE_P;
            for (int g0 = 0; g0 < TILE_P; g0 += GROUP_P) {
                __syncthreads();
#pragma unroll
                for (int e = tid; e < GROUP_P * CIN; e += 256) {
                    int p = e >> 5;
                    int c = e & 31;
                    int j = base + g0 + p;
                    if (j < cnt) {
                        int2 r = rules_k[j];
                        sf[p][c] = features[(size_t)r.x * CIN + c];
                        if (c == 0) sflat[p] = r.y;
                    }
                }
                __syncthreads();

#pragma unroll
                for (int pp = 0; pp < GROUP_P; pp += 4) {
                    int p = pbase + pp;
                    int j = base + g0 + p;
                    if (j < cnt) {   // uniform across each 64-thread group (and warp)
                        unsigned long long acc = 0ull;
                        const ulonglong2* f2 = (const ulonglong2*)sf[p];
#pragma unroll
                        for (int q = 0; q < 8; q++) {
                            ulonglong2 u = f2[q];
                            FFMA2(acc, u.x, w2[2 * q + 0], acc);
                            FFMA2(acc, u.y, w2[2 * q + 1], acc);
                        }
                        float a0, a1;
                        asm("mov.b64 {%0, %1}, %2;" : "=f"(a0), "=f"(a1) : "l"(acc));
                        float v0 = a0 + a1;
                        // collect 4 adjacent couts into lanes with cout%4==0
                        float v1 = __shfl_down_sync(0xffffffffu, v0, 1);
                        float v2 = __shfl_down_sync(0xffffffffu, v0, 2);
                        float v3 = __shfl_down_sync(0xffffffffu, v0, 3);
                        if ((cout & 3) == 0) {
                            const float* dst = out + (size_t)sflat[p] * COUT + cout;
                            asm volatile(
                                "{ .reg .u64 pg; cvta.to.global.u64 pg, %0;\n\t"
                                "  red.global.add.v4.f32 [pg], {%1, %2, %3, %4}; }"
                                :: "l"(dst), "f"(v0), "f"(v1), "f"(v2), "f"(v3)
                                : "memory");
                        }
                    }
                }
            }
        }
    }

    // Epilogue: last finished block resets counters for the next replay.
    __syncthreads();
    if (tid == 0) {
        int d = atomicAdd(&g_done, 1);
        if (d == GEMM_GX * KVOL - 1) {
#pragma unroll
            for (int i = 0; i < KVOL; i++) g_cnt[i * 128] = 0;
            g_done = 0;
        }
    }
}

// ---------------- launch ----------------
extern "C" void kernel_launch(void* const* d_in, const int* in_sizes, int n_in,
                              void* d_out, int out_size) {
    const float* features = (const float*)d_in[0];
    const int*   coords   = (const int*)d_in[1];
    const float* weight   = (const float*)d_in[2];
    float*       out      = (float*)d_out;

    long long n4 = (long long)out_size / 4;
    zero_and_build<<<BUILD_BLOCKS + ZERO_BLOCKS, 256>>>((float4*)out, n4, coords);

    dim3 grid(GEMM_GX, KVOL);
    gather_gemm_scatter<<<grid, 256>>>(features, weight, out);
}

// round 7
// speedup vs baseline: 1.2359x; 1.0316x over previous
#include <cuda_runtime.h>
#include <cstdint>

// ---------------- problem constants ----------------
#define NNZ      220939
#define CIN      32
#define COUT     64
#define KVOL     27
#define OUT_X    11
#define OUT_Y    400
#define OUT_Z    352

// ---------------- device scratch (static, allocation-free) ----------------
__device__ int2 g_rules[(size_t)KVOL * NNZ];          // 47.7 MB rulebook
__device__ int  g_cnt[KVOL * 128];                    // counters, 512B apart
__device__ int  g_done;                               // gemm completion ctr

// ---------------- kernel A: fused zero-output + build-rulebook ---------------
#define BUILD_BLOCKS 864   // ceil(NNZ/256)
#define ZERO_BLOCKS  4096

__global__ void zero_and_build(float4* __restrict__ out4, long long n4,
                               const int* __restrict__ coords) {
    if (blockIdx.x >= BUILD_BLOCKS) {
        long long i = (long long)(blockIdx.x - BUILD_BLOCKS) * blockDim.x + threadIdx.x;
        long long step = (long long)ZERO_BLOCKS * blockDim.x;
        float4 z = make_float4(0.f, 0.f, 0.f, 0.f);
        for (; i < n4; i += step) out4[i] = z;
        return;
    }

    int i    = blockIdx.x * blockDim.x + threadIdx.x;
    int lane = threadIdx.x & 31;
    bool active = (i < NNZ);

    int cx = 0, cy = 0, cz = 0;
    if (active) {
        cx = coords[i * 3 + 0];
        cy = coords[i * 3 + 1];
        cz = coords[i * 3 + 2];
    }

    bool vX[3], vY[3], vZ[3];
    int  qX[3], qY[3], qZ[3];
#pragma unroll
    for (int o = 0; o < 3; o++) {
        int ox = cx + 1 - o; vX[o] = (ox >= 0) && !(ox & 1) && ((ox >> 1) < OUT_X); qX[o] = ox >> 1;
        int oy = cy + 1 - o; vY[o] = (oy >= 0) && !(oy & 1) && ((oy >> 1) < OUT_Y); qY[o] = oy >> 1;
        int oz = cz + 1 - o; vZ[o] = (oz >= 0) && !(oz & 1) && ((oz >> 1) < OUT_Z); qZ[o] = oz >> 1;
    }

#pragma unroll
    for (int kx = 0; kx < 3; kx++) {
#pragma unroll
        for (int ky = 0; ky < 3; ky++) {
#pragma unroll
            for (int kz = 0; kz < 3; kz++) {
                int k = (kx * 3 + ky) * 3 + kz;
                bool valid = active && vX[kx] && vY[ky] && vZ[kz];
                int flat = 0;
                if (valid) flat = (qX[kx] * OUT_Y + qY[ky]) * OUT_Z + qZ[kz];

                unsigned mask = __ballot_sync(0xffffffffu, valid);
                if (mask) {
                    int leader = __ffs(mask) - 1;
                    int base = 0;
                    if (lane == leader)
                        base = atomicAdd(&g_cnt[k * 128], __popc(mask));
                    base = __shfl_sync(0xffffffffu, base, leader);
                    if (valid) {
                        int pos = base + __popc(mask & ((1u << lane) - 1u));
                        g_rules[(size_t)k * NNZ + pos] = make_int2(i, flat);
                    }
                }
            }
        }
    }
}

// ---------------- kernel B: tf32 MMA gather-GEMM-scatter ---------------------
// Block 256 = 8 warps. Tile = 64 points x 64 couts.
//   warp w: slab = w&3 (16 rows), half = w>>2 (32 couts = 4 n-tiles).
// Weights for this block's offset live in 32 tf32 B-fragment registers
// (loaded once). Features staged per tile in shared (tf32-converted, stride
// 36 words -> bank-conflict-free A-fragment LDS). Inner loop: 4 k-steps x
// (4 LDS + 4 mma.m16n8k8.tf32). Scatter: pair C columns via 2 independent
// shfls -> red.global.add.v4.f32 (16B per op).
#define TILE_P  64
#define GEMM_GX 448

#define MMA_TF32(c0,c1,c2,c3, a0,a1,a2,a3, b0,b1) \
    asm("mma.sync.aligned.m16n8k8.row.col.f32.tf32.tf32.f32 " \
        "{%0,%1,%2,%3}, {%4,%5,%6,%7}, {%8,%9}, {%0,%1,%2,%3};" \
        : "+f"(c0), "+f"(c1), "+f"(c2), "+f"(c3) \
        : "r"(a0), "r"(a1), "r"(a2), "r"(a3), "r"(b0), "r"(b1))

__device__ __forceinline__ unsigned f2tf32(float f) {
    unsigned u;
    asm("cvt.rna.tf32.f32 %0, %1;" : "=r"(u) : "f"(f));
    return u;
}

__global__ __launch_bounds__(256)
void gather_gemm_scatter(const float* __restrict__ features,
                         const float* __restrict__ weight,
                         float* __restrict__ out) {
    const int k   = blockIdx.y;
    const int cnt = g_cnt[k * 128];

    const int tid  = threadIdx.x;
    const int w    = tid >> 5;
    const int lane = tid & 31;
    const int g    = lane >> 2;      // group id: A rows / B cols
    const int t    = lane & 3;       // thread-in-group: A cols / B rows
    const int slab = w & 3;
    const int half = w >> 2;

    __shared__ unsigned sfu[TILE_P * 36];   // tf32 features, stride 36 words
    __shared__ int      sflat[TILE_P];

    if (cnt > 0) {
        // ---- B fragments: W[k][cin][cout] for this warp's 4 n-tiles --------
        unsigned B0[4][4], B1[4][4];        // [n-tile j][k-step kk]
        {
            const float* wk = weight + (size_t)k * (CIN * COUT);
#pragma unroll
            for (int j = 0; j < 4; j++) {
                int n = half * 32 + j * 8 + g;
#pragma unroll
                for (int kk = 0; kk < 4; kk++) {
                    int k0 = kk * 8 + t;
                    B0[j][kk] = f2tf32(wk[k0 * COUT + n]);
                    B1[j][kk] = f2tf32(wk[(k0 + 4) * COUT + n]);
                }
            }
        }

        const int2* rules_k = g_rules + (size_t)k * NNZ;

        for (int tile = blockIdx.x; tile * TILE_P < cnt; tile += GEMM_GX) {
            const int base = tile * TILE_P;

            __syncthreads();
            // ---- stage 64 points (coalesced 128B per point), cvt to tf32 ---
#pragma unroll
            for (int e = tid; e < TILE_P * CIN; e += 256) {
                int p = e >> 5;
                int c = e & 31;
                int jj = base + p;
                if (jj >= cnt) jj = cnt - 1;     // clamp; rows predicated later
                int2 r = rules_k[jj];
                sfu[p * 36 + c] = f2tf32(features[(size_t)r.x * CIN + c]);
                if (c == 0) sflat[p] = r.y;
            }
            __syncthreads();

            // ---- MMA: 16 rows x 32 couts per warp ---------------------------
            float C0[4], C1[4], C2[4], C3[4];
#pragma unroll
            for (int j = 0; j < 4; j++) { C0[j] = C1[j] = C2[j] = C3[j] = 0.f; }

            const int r0 = slab * 16 + g;       // local rows r0, r0+8
#pragma unroll
            for (int kk = 0; kk < 4; kk++) {
                int cbase = kk * 8 + t;
                unsigned a0 = sfu[r0 * 36 + cbase];
                unsigned a1 = sfu[(r0 + 8) * 36 + cbase];
                unsigned a2 = sfu[r0 * 36 + cbase + 4];
                unsigned a3 = sfu[(r0 + 8) * 36 + cbase + 4];
#pragma unroll
                for (int j = 0; j < 4; j++)
                    MMA_TF32(C0[j], C1[j], C2[j], C3[j],
                             a0, a1, a2, a3, B0[j][kk], B1[j][kk]);
            }

            // ---- scatter: pair columns -> red.v4 ----------------------------
            const bool v0 = (base + r0)     < cnt;
            const bool v1 = (base + r0 + 8) < cnt;
            const int  f0 = sflat[r0];
            const int  f1 = sflat[r0 + 8];
            const int  colbase = half * 32 + 2 * t;   // t even -> 0 or 4
#pragma unroll
            for (int j = 0; j < 4; j++) {
                float x0 = __shfl_down_sync(0xffffffffu, C0[j], 1);
                float x1 = __shfl_down_sync(0xffffffffu, C1[j], 1);
                float x2 = __shfl_down_sync(0xffffffffu, C2[j], 1);
                float x3 = __shfl_down_sync(0xffffffffu, C3[j], 1);
                if ((t & 1) == 0) {
                    if (v0) {
                        const float* dst = out + (size_t)f0 * COUT + colbase + j * 8;
                        asm volatile(
                            "{ .reg .u64 pg; cvta.to.global.u64 pg, %0;\n\t"
                            "  red.global.add.v4.f32 [pg], {%1, %2, %3, %4}; }"
                            :: "l"(dst), "f"(C0[j]), "f"(C1[j]), "f"(x0), "f"(x1)
                            : "memory");
                    }
                    if (v1) {
                        const float* dst = out + (size_t)f1 * COUT + colbase + j * 8;
                        asm volatile(
                            "{ .reg .u64 pg; cvta.to.global.u64 pg, %0;\n\t"
                            "  red.global.add.v4.f32 [pg], {%1, %2, %3, %4}; }"
                            :: "l"(dst), "f"(C2[j]), "f"(C3[j]), "f"(x2), "f"(x3)
                            : "memory");
                    }
                }
            }
        }
    }

    // ---- epilogue: last finished block resets counters for next replay -----
    __syncthreads();
    if (tid == 0) {
        int d = atomicAdd(&g_done, 1);
        if (d == GEMM_GX * KVOL - 1) {
#pragma unroll
            for (int i = 0; i < KVOL; i++) g_cnt[i * 128] = 0;
            g_done = 0;
        }
    }
}

// ---------------- launch ----------------
extern "C" void kernel_launch(void* const* d_in, const int* in_sizes, int n_in,
                              void* d_out, int out_size) {
    const float* features = (const float*)d_in[0];
    const int*   coords   = (const int*)d_in[1];
    const float* weight   = (const float*)d_in[2];
    float*       out      = (float*)d_out;

    long long n4 = (long long)out_size / 4;
    zero_and_build<<<BUILD_BLOCKS + ZERO_BLOCKS, 256>>>((float4*)out, n4, coords);

    dim3 grid(GEMM_GX, KVOL);
    gather_gemm_scatter<<<grid, 256>>>(features, weight, out);
}

// round 8
// speedup vs baseline: 2.1531x; 1.7421x over previous
#include <cuda_runtime.h>
#include <cstdint>

// ---------------- problem constants ----------------
#define NNZ      220939
#define CIN      32
#define COUT     64
#define KVOL     27
#define OUT_X    11
#define OUT_Y    400
#define OUT_Z    352

// ---------------- device scratch (static, allocation-free) ----------------
__device__ int2 g_rules[(size_t)KVOL * NNZ];          // 47.7 MB rulebook
__device__ int  g_cnt[KVOL * 128];                    // counters, 512B apart
__device__ int  g_done;                               // gemm completion ctr

// ---------------- kernel A: fused zero-output + build-rulebook ---------------
// Zero blocks FIRST (0..ZERO_BLOCKS-1) so the DRAM fill starts at full width;
// build blocks trail and hide inside the zero tail.
#define ZERO_BLOCKS  4096
#define BUILD_BLOCKS 864   // ceil(NNZ/256)

__global__ void zero_and_build(float4* __restrict__ out4, long long n4,
                               const int* __restrict__ coords) {
    if (blockIdx.x < ZERO_BLOCKS) {
        long long i = (long long)blockIdx.x * blockDim.x + threadIdx.x;
        long long step = (long long)ZERO_BLOCKS * blockDim.x;
        float4 z = make_float4(0.f, 0.f, 0.f, 0.f);
        for (; i < n4; i += step) out4[i] = z;
        return;
    }

    int i    = (blockIdx.x - ZERO_BLOCKS) * blockDim.x + threadIdx.x;
    int lane = threadIdx.x & 31;
    bool active = (i < NNZ);

    int cx = 0, cy = 0, cz = 0;
    if (active) {
        cx = coords[i * 3 + 0];
        cy = coords[i * 3 + 1];
        cz = coords[i * 3 + 2];
    }

    bool vX[3], vY[3], vZ[3];
    int  qX[3], qY[3], qZ[3];
#pragma unroll
    for (int o = 0; o < 3; o++) {
        int ox = cx + 1 - o; vX[o] = (ox >= 0) && !(ox & 1) && ((ox >> 1) < OUT_X); qX[o] = ox >> 1;
        int oy = cy + 1 - o; vY[o] = (oy >= 0) && !(oy & 1) && ((oy >> 1) < OUT_Y); qY[o] = oy >> 1;
        int oz = cz + 1 - o; vZ[o] = (oz >= 0) && !(oz & 1) && ((oz >> 1) < OUT_Z); qZ[o] = oz >> 1;
    }

#pragma unroll
    for (int kx = 0; kx < 3; kx++) {
#pragma unroll
        for (int ky = 0; ky < 3; ky++) {
#pragma unroll
            for (int kz = 0; kz < 3; kz++) {
                int k = (kx * 3 + ky) * 3 + kz;
                bool valid = active && vX[kx] && vY[ky] && vZ[kz];
                int flat = 0;
                if (valid) flat = (qX[kx] * OUT_Y + qY[ky]) * OUT_Z + qZ[kz];

                unsigned mask = __ballot_sync(0xffffffffu, valid);
                if (mask) {
                    int leader = __ffs(mask) - 1;
                    int base = 0;
                    if (lane == leader)
                        base = atomicAdd(&g_cnt[k * 128], __popc(mask));
                    base = __shfl_sync(0xffffffffu, base, leader);
                    if (valid) {
                        int pos = base + __popc(mask & ((1u << lane) - 1u));
                        g_rules[(size_t)k * NNZ + pos] = make_int2(i, flat);
                    }
                }
            }
        }
    }
}

// ---------------- kernel B: tf32 MMA gather-GEMM-scatter ---------------------
// Block 256 = 8 warps. Tile = 64 points x 64 couts; ~7 tiles per block
// (GEMM_GX=64) so weight setup amortizes. W[k] staged ONCE per block into
// shared (coalesced float4, tf32-converted), B-fragments pulled via LDS.
// Features staged per tile as float4 -> tf32 into stride-36 shared (conflict-
// free A LDS). Inner loop: 4 k-steps x 4 n-tiles of mma.m16n8k8.tf32.
// Scatter: pair C columns via 2 independent shfls -> red.global.add.v4.f32.
#define TILE_P  64
#define GEMM_GX 64

#define MMA_TF32(c0,c1,c2,c3, a0,a1,a2,a3, b0,b1) \
    asm("mma.sync.aligned.m16n8k8.row.col.f32.tf32.tf32.f32 " \
        "{%0,%1,%2,%3}, {%4,%5,%6,%7}, {%8,%9}, {%0,%1,%2,%3};" \
        : "+f"(c0), "+f"(c1), "+f"(c2), "+f"(c3) \
        : "r"(a0), "r"(a1), "r"(a2), "r"(a3), "r"(b0), "r"(b1))

__device__ __forceinline__ unsigned f2tf32(float f) {
    unsigned u;
    asm("cvt.rna.tf32.f32 %0, %1;" : "=r"(u) : "f"(f));
    return u;
}

__global__ __launch_bounds__(256)
void gather_gemm_scatter(const float* __restrict__ features,
                         const float* __restrict__ weight,
                         float* __restrict__ out) {
    const int k   = blockIdx.y;
    const int cnt = g_cnt[k * 128];

    const int tid  = threadIdx.x;
    const int w    = tid >> 5;
    const int lane = tid & 31;
    const int g    = lane >> 2;      // group id: A rows / B cols
    const int t    = lane & 3;       // thread-in-group: A cols / B rows
    const int slab = w & 3;
    const int half = w >> 2;

    __shared__ unsigned swt[CIN * COUT];    // tf32 weights [cin][cout], 8KB
    __shared__ unsigned sfu[TILE_P * 36];   // tf32 features, stride 36 words
    __shared__ int      sflat[TILE_P];

    if (cnt > 0) {
        // ---- stage W[k] into shared (coalesced), convert to tf32 -----------
        {
            const float4* wk4 = (const float4*)(weight + (size_t)k * (CIN * COUT));
#pragma unroll
            for (int e = tid; e < CIN * COUT / 4; e += 256) {
                float4 v = wk4[e];
                swt[e * 4 + 0] = f2tf32(v.x);
                swt[e * 4 + 1] = f2tf32(v.y);
                swt[e * 4 + 2] = f2tf32(v.z);
                swt[e * 4 + 3] = f2tf32(v.w);
            }
        }
        __syncthreads();

        // ---- B fragments from shared ---------------------------------------
        unsigned B0[4][4], B1[4][4];        // [n-tile j][k-step kk]
#pragma unroll
        for (int j = 0; j < 4; j++) {
            int n = half * 32 + j * 8 + g;
#pragma unroll
            for (int kk = 0; kk < 4; kk++) {
                int k0 = kk * 8 + t;
                B0[j][kk] = swt[k0 * COUT + n];
                B1[j][kk] = swt[(k0 + 4) * COUT + n];
            }
        }

        const int2* rules_k = g_rules + (size_t)k * NNZ;

        for (int tile = blockIdx.x; tile * TILE_P < cnt; tile += GEMM_GX) {
            const int base = tile * TILE_P;

            __syncthreads();
            // ---- stage 64 points: 2x LDG.128 per thread, cvt to tf32 -------
#pragma unroll
            for (int e = tid; e < TILE_P * 8; e += 256) {
                int p  = e >> 3;
                int c4 = e & 7;
                int jj = base + p;
                if (jj >= cnt) jj = cnt - 1;     // clamp; rows predicated later
                int2 r = rules_k[jj];
                float4 v = ((const float4*)(features + (size_t)r.x * CIN))[c4];
                unsigned* d = &sfu[p * 36 + c4 * 4];
                d[0] = f2tf32(v.x);
                d[1] = f2tf32(v.y);
                d[2] = f2tf32(v.z);
                d[3] = f2tf32(v.w);
                if (c4 == 0) sflat[p] = r.y;
            }
            __syncthreads();

            // ---- MMA: 16 rows x 32 couts per warp ---------------------------
            float C0[4], C1[4], C2[4], C3[4];
#pragma unroll
            for (int j = 0; j < 4; j++) { C0[j] = C1[j] = C2[j] = C3[j] = 0.f; }

            const int r0 = slab * 16 + g;       // local rows r0, r0+8
#pragma unroll
            for (int kk = 0; kk < 4; kk++) {
                int cbase = kk * 8 + t;
                unsigned a0 = sfu[r0 * 36 + cbase];
                unsigned a1 = sfu[(r0 + 8) * 36 + cbase];
                unsigned a2 = sfu[r0 * 36 + cbase + 4];
                unsigned a3 = sfu[(r0 + 8) * 36 + cbase + 4];
#pragma unroll
                for (int j = 0; j < 4; j++)
                    MMA_TF32(C0[j], C1[j], C2[j], C3[j],
                             a0, a1, a2, a3, B0[j][kk], B1[j][kk]);
            }

            // ---- scatter: pair columns -> red.v4 ----------------------------
            const bool v0 = (base + r0)     < cnt;
            const bool v1 = (base + r0 + 8) < cnt;
            const int  f0 = sflat[r0];
            const int  f1 = sflat[r0 + 8];
            const int  colbase = half * 32 + 2 * t;   // t even -> 0 or 4
#pragma unroll
            for (int j = 0; j < 4; j++) {
                float x0 = __shfl_down_sync(0xffffffffu, C0[j], 1);
                float x1 = __shfl_down_sync(0xffffffffu, C1[j], 1);
                float x2 = __shfl_down_sync(0xffffffffu, C2[j], 1);
                float x3 = __shfl_down_sync(0xffffffffu, C3[j], 1);
                if ((t & 1) == 0) {
                    if (v0) {
                        const float* dst = out + (size_t)f0 * COUT + colbase + j * 8;
                        asm volatile(
                            "{ .reg .u64 pg; cvta.to.global.u64 pg, %0;\n\t"
                            "  red.global.add.v4.f32 [pg], {%1, %2, %3, %4}; }"
                            :: "l"(dst), "f"(C0[j]), "f"(C1[j]), "f"(x0), "f"(x1)
                            : "memory");
                    }
                    if (v1) {
                        const float* dst = out + (size_t)f1 * COUT + colbase + j * 8;
                        asm volatile(
                            "{ .reg .u64 pg; cvta.to.global.u64 pg, %0;\n\t"
                            "  red.global.add.v4.f32 [pg], {%1, %2, %3, %4}; }"
                            :: "l"(dst), "f"(C2[j]), "f"(C3[j]), "f"(x2), "f"(x3)
                            : "memory");
                    }
                }
            }
        }
    }

    // ---- epilogue: last finished block resets counters for next replay -----
    __syncthreads();
    if (tid == 0) {
        int d = atomicAdd(&g_done, 1);
        if (d == GEMM_GX * KVOL - 1) {
#pragma unroll
            for (int i = 0; i < KVOL; i++) g_cnt[i * 128] = 0;
            g_done = 0;
        }
    }
}

// ---------------- launch ----------------
extern "C" void kernel_launch(void* const* d_in, const int* in_sizes, int n_in,
                              void* d_out, int out_size) {
    const float* features = (const float*)d_in[0];
    const int*   coords   = (const int*)d_in[1];
    const float* weight   = (const float*)d_in[2];
    float*       out      = (float*)d_out;

    long long n4 = (long long)out_size / 4;
    zero_and_build<<<ZERO_BLOCKS + BUILD_BLOCKS, 256>>>((float4*)out, n4, coords);

    dim3 grid(GEMM_GX, KVOL);
    gather_gemm_scatter<<<grid, 256>>>(features, weight, out);
}

// round 9
// speedup vs baseline: 2.2572x; 1.0483x over previous
#include <cuda_runtime.h>
#include <cstdint>

// ---------------- problem constants ----------------
#define NNZ      220939
#define CIN      32
#define COUT     64
#define KVOL     27
#define OUT_X    11
#define OUT_Y    400
#define OUT_Z    352

// ---------------- device scratch (static, allocation-free) ----------------
__device__ int2 g_rules[(size_t)KVOL * NNZ];          // 47.7 MB rulebook
__device__ int  g_cnt[KVOL * 128];                    // counters, 512B apart
__device__ int  g_done;                               // gemm completion ctr

// ---------------- kernel A: fused zero-output + build-rulebook ---------------
#define ZERO_BLOCKS  4096
#define BUILD_BLOCKS 864   // ceil(NNZ/256)

__global__ void zero_and_build(float4* __restrict__ out4, long long n4,
                               const int* __restrict__ coords) {
    if (blockIdx.x < ZERO_BLOCKS) {
        long long i = (long long)blockIdx.x * blockDim.x + threadIdx.x;
        long long step = (long long)ZERO_BLOCKS * blockDim.x;
        float4 z = make_float4(0.f, 0.f, 0.f, 0.f);
        for (; i < n4; i += step) out4[i] = z;
        return;
    }

    int i    = (blockIdx.x - ZERO_BLOCKS) * blockDim.x + threadIdx.x;
    int lane = threadIdx.x & 31;
    bool active = (i < NNZ);

    int cx = 0, cy = 0, cz = 0;
    if (active) {
        cx = coords[i * 3 + 0];
        cy = coords[i * 3 + 1];
        cz = coords[i * 3 + 2];
    }

    bool vX[3], vY[3], vZ[3];
    int  qX[3], qY[3], qZ[3];
#pragma unroll
    for (int o = 0; o < 3; o++) {
        int ox = cx + 1 - o; vX[o] = (ox >= 0) && !(ox & 1) && ((ox >> 1) < OUT_X); qX[o] = ox >> 1;
        int oy = cy + 1 - o; vY[o] = (oy >= 0) && !(oy & 1) && ((oy >> 1) < OUT_Y); qY[o] = oy >> 1;
        int oz = cz + 1 - o; vZ[o] = (oz >= 0) && !(oz & 1) && ((oz >> 1) < OUT_Z); qZ[o] = oz >> 1;
    }

#pragma unroll
    for (int kx = 0; kx < 3; kx++) {
#pragma unroll
        for (int ky = 0; ky < 3; ky++) {
#pragma unroll
            for (int kz = 0; kz < 3; kz++) {
                int k = (kx * 3 + ky) * 3 + kz;
                bool valid = active && vX[kx] && vY[ky] && vZ[kz];
                int flat = 0;
                if (valid) flat = (qX[kx] * OUT_Y + qY[ky]) * OUT_Z + qZ[kz];

                unsigned mask = __ballot_sync(0xffffffffu, valid);
                if (mask) {
                    int leader = __ffs(mask) - 1;
                    int base = 0;
                    if (lane == leader)
                        base = atomicAdd(&g_cnt[k * 128], __popc(mask));
                    base = __shfl_sync(0xffffffffu, base, leader);
                    if (valid) {
                        int pos = base + __popc(mask & ((1u << lane) - 1u));
                        g_rules[(size_t)k * NNZ + pos] = make_int2(i, flat);
                    }
                }
            }
        }
    }
}

// ---------------- kernel B: tf32 MMA, cp.async-pipelined ---------------------
// Block 256 = 8 warps, tile = 64 points x 64 couts, ~7 tiles/block (GX=64).
// W[k] staged once into shared (tf32). Features flow via a 2-deep cp.async
// pipeline (16B LDGSTS chunks into double-buffered stride-36 smem); rule
// entries for the tile being issued are prefetched into registers during the
// previous tile's compute. fp32->tf32 conversion happens at A-fragment load.
// Scatter: paired C columns -> red.global.add.v4.f32. Epilogue resets
// counters for the next graph replay.
#define TILE_P  64
#define GEMM_GX 64

#define MMA_TF32(c0,c1,c2,c3, a0,a1,a2,a3, b0,b1) \
    asm("mma.sync.aligned.m16n8k8.row.col.f32.tf32.tf32.f32 " \
        "{%0,%1,%2,%3}, {%4,%5,%6,%7}, {%8,%9}, {%0,%1,%2,%3};" \
        : "+f"(c0), "+f"(c1), "+f"(c2), "+f"(c3) \
        : "r"(a0), "r"(a1), "r"(a2), "r"(a3), "r"(b0), "r"(b1))

__device__ __forceinline__ unsigned f2tf32(float f) {
    unsigned u;
    asm("cvt.rna.tf32.f32 %0, %1;" : "=r"(u) : "f"(f));
    return u;
}

__device__ __forceinline__ void cp16(unsigned smem, const void* gmem) {
    asm volatile("cp.async.ca.shared.global [%0], [%1], 16;"
                 :: "r"(smem), "l"(gmem));
}
#define CP_COMMIT() asm volatile("cp.async.commit_group;")
#define CP_WAIT0()  asm volatile("cp.async.wait_group 0;")
#define CP_WAIT1()  asm volatile("cp.async.wait_group 1;")

__global__ __launch_bounds__(256)
void gather_gemm_scatter(const float* __restrict__ features,
                         const float* __restrict__ weight,
                         float* __restrict__ out) {
    const int k   = blockIdx.y;
    const int cnt = g_cnt[k * 128];

    const int tid  = threadIdx.x;
    const int w    = tid >> 5;
    const int lane = tid & 31;
    const int g    = lane >> 2;      // group id: A rows / B cols
    const int t    = lane & 3;       // thread-in-group: A cols / B rows
    const int slab = w & 3;
    const int half = w >> 2;

    __shared__ unsigned swt[CIN * COUT];          // tf32 weights, 8KB
    __shared__ float    sfu[2][TILE_P * 36];      // fp32 features, double buf
    __shared__ int      sflat[2][TILE_P];

    // number of tiles this block owns
    int nt = 0;
    {
        int tiles = (cnt + TILE_P - 1) / TILE_P;
        if ((int)blockIdx.x < tiles)
            nt = (tiles - blockIdx.x + GEMM_GX - 1) / GEMM_GX;
    }

    if (nt > 0) {
        // ---- stage W[k] into shared (coalesced), convert to tf32 -----------
        {
            const float4* wk4 = (const float4*)(weight + (size_t)k * (CIN * COUT));
#pragma unroll
            for (int e = tid; e < CIN * COUT / 4; e += 256) {
                float4 v = wk4[e];
                swt[e * 4 + 0] = f2tf32(v.x);
                swt[e * 4 + 1] = f2tf32(v.y);
                swt[e * 4 + 2] = f2tf32(v.z);
                swt[e * 4 + 3] = f2tf32(v.w);
            }
        }

        const int2* rules_k = g_rules + (size_t)k * NNZ;
        const int p0 = tid >> 3;              // rows this thread stages
        const int p1 = 32 + (tid >> 3);
        const int c4 = tid & 7;               // 16B chunk within row

        // rule prefetch + feature issue helpers (per-thread)
        auto load_rules = [&](int tile, int2& ra, int2& rb) {
            int base = tile * TILE_P;
            int ja = base + p0; if (ja >= cnt) ja = cnt - 1;
            int jb = base + p1; if (jb >= cnt) jb = cnt - 1;
            ra = __ldg(&rules_k[ja]);
            rb = __ldg(&rules_k[jb]);
        };
        auto issue_feat = [&](int buf, int2 ra, int2 rb) {
            unsigned sb = (unsigned)__cvta_generic_to_shared(&sfu[buf][0]);
            cp16(sb + (p0 * 36 + c4 * 4) * 4,
                 features + (size_t)ra.x * CIN + c4 * 4);
            cp16(sb + (p1 * 36 + c4 * 4) * 4,
                 features + (size_t)rb.x * CIN + c4 * 4);
            if (c4 == 0) { sflat[buf][p0] = ra.y; sflat[buf][p1] = rb.y; }
        };

        // ---- prolog: issue tiles 0 and 1 -----------------------------------
        int2 ra, rb;
        load_rules(blockIdx.x, ra, rb);
        issue_feat(0, ra, rb);
        CP_COMMIT();
        if (nt > 1) {
            load_rules(blockIdx.x + GEMM_GX, ra, rb);
            issue_feat(1, ra, rb);
            CP_COMMIT();
        }
        __syncthreads();   // swt ready (also joins prolog)

        // ---- B fragments from shared ---------------------------------------
        unsigned B0[4][4], B1[4][4];
#pragma unroll
        for (int j = 0; j < 4; j++) {
            int n = half * 32 + j * 8 + g;
#pragma unroll
            for (int kk = 0; kk < 4; kk++) {
                int k0 = kk * 8 + t;
                B0[j][kk] = swt[k0 * COUT + n];
                B1[j][kk] = swt[(k0 + 4) * COUT + n];
            }
        }

        const int r0 = slab * 16 + g;         // local rows r0, r0+8

        for (int i = 0; i < nt; i++) {
            const int tile = blockIdx.x + i * GEMM_GX;
            const int buf  = i & 1;

            // rules for tile i+2 (issued after compute)
            bool has2 = (i + 2 < nt);
            if (has2) load_rules(blockIdx.x + (i + 2) * GEMM_GX, ra, rb);

            if (i + 1 < nt) CP_WAIT1(); else CP_WAIT0();
            __syncthreads();                   // buf ready, prev compute done

            // ---- MMA: 16 rows x 32 couts per warp ---------------------------
            float C0[4], C1[4], C2[4], C3[4];
#pragma unroll
            for (int j = 0; j < 4; j++) { C0[j] = C1[j] = C2[j] = C3[j] = 0.f; }

            const float* fb = sfu[buf];
#pragma unroll
            for (int kk = 0; kk < 4; kk++) {
                int cbase = kk * 8 + t;
                unsigned a0 = f2tf32(fb[r0 * 36 + cbase]);
                unsigned a1 = f2tf32(fb[(r0 + 8) * 36 + cbase]);
                unsigned a2 = f2tf32(fb[r0 * 36 + cbase + 4]);
                unsigned a3 = f2tf32(fb[(r0 + 8) * 36 + cbase + 4]);
#pragma unroll
                for (int j = 0; j < 4; j++)
                    MMA_TF32(C0[j], C1[j], C2[j], C3[j],
                             a0, a1, a2, a3, B0[j][kk], B1[j][kk]);
            }

            // ---- scatter: pair columns -> red.v4 ----------------------------
            const int  base = tile * TILE_P;
            const bool v0 = (base + r0)     < cnt;
            const bool v1 = (base + r0 + 8) < cnt;
            const int  f0 = sflat[buf][r0];
            const int  f1 = sflat[buf][r0 + 8];
            const int  colbase = half * 32 + 2 * t;
#pragma unroll
            for (int j = 0; j < 4; j++) {
                float x0 = __shfl_down_sync(0xffffffffu, C0[j], 1);
                float x1 = __shfl_down_sync(0xffffffffu, C1[j], 1);
                float x2 = __shfl_down_sync(0xffffffffu, C2[j], 1);
                float x3 = __shfl_down_sync(0xffffffffu, C3[j], 1);
                if ((t & 1) == 0) {
                    if (v0) {
                        const float* dst = out + (size_t)f0 * COUT + colbase + j * 8;
                        asm volatile(
                            "{ .reg .u64 pg; cvta.to.global.u64 pg, %0;\n\t"
                            "  red.global.add.v4.f32 [pg], {%1, %2, %3, %4}; }"
                            :: "l"(dst), "f"(C0[j]), "f"(C1[j]), "f"(x0), "f"(x1)
                            : "memory");
                    }
                    if (v1) {
                        const float* dst = out + (size_t)f1 * COUT + colbase + j * 8;
                        asm volatile(
                            "{ .reg .u64 pg; cvta.to.global.u64 pg, %0;\n\t"
                            "  red.global.add.v4.f32 [pg], {%1, %2, %3, %4}; }"
                            :: "l"(dst), "f"(C2[j]), "f"(C3[j]), "f"(x2), "f"(x3)
                            : "memory");
                    }
                }
            }

            // issue features for tile i+2 into buf (done reading it next sync)
            if (has2) {
                __syncthreads();               // everyone done reading buf
                issue_feat(buf, ra, rb);
                CP_COMMIT();
            }
        }
    }

    // ---- epilogue: last finished block resets counters for next replay -----
    __syncthreads();
    if (tid == 0) {
        int d = atomicAdd(&g_done, 1);
        if (d == GEMM_GX * KVOL - 1) {
#pragma unroll
            for (int i = 0; i < KVOL; i++) g_cnt[i * 128] = 0;
            g_done = 0;
        }
    }
}

// ---------------- launch ----------------
extern "C" void kernel_launch(void* const* d_in, const int* in_sizes, int n_in,
                              void* d_out, int out_size) {
    const float* features = (const float*)d_in[0];
    const int*   coords   = (const int*)d_in[1];
    const float* weight   = (const float*)d_in[2];
    float*       out      = (float*)d_out;

    long long n4 = (long long)out_size / 4;
    zero_and_build<<<ZERO_BLOCKS + BUILD_BLOCKS, 256>>>((float4*)out, n4, coords);

    dim3 grid(GEMM_GX, KVOL);
    gather_gemm_scatter<<<grid, 256>>>(features, weight, out);
}